// round 1
// baseline (speedup 1.0000x reference)
#include <cuda_runtime.h>
#include <math.h>

#define EMB   768
#define DFF   3072
#define NTOK  16384
#define HEADS 12
#define HD    64
#define SEQ   1024
#define BATCH 16

// ---------------- scratch (no allocations allowed) ----------------
__device__ float g_h  [NTOK * EMB];
__device__ float g_q  [NTOK * EMB];
__device__ float g_k  [NTOK * EMB];
__device__ float g_v  [NTOK * EMB];
__device__ float g_ctx[NTOK * EMB];
__device__ float g_x1 [NTOK * EMB];
__device__ float g_h2 [NTOK * EMB];
__device__ float g_ff [NTOK * DFF];

// ---------------- block reduction helper ----------------
__device__ __forceinline__ float block_reduce_sum(float v, float* red) {
    #pragma unroll
    for (int off = 16; off > 0; off >>= 1)
        v += __shfl_xor_sync(0xffffffffu, v, off);
    int w = threadIdx.x >> 5;
    if ((threadIdx.x & 31) == 0) red[w] = v;
    __syncthreads();
    if (threadIdx.x < 32) {
        float t = (threadIdx.x < 8) ? red[threadIdx.x] : 0.0f;
        #pragma unroll
        for (int off = 4; off > 0; off >>= 1)
            t += __shfl_xor_sync(0xffffffffu, t, off);
        if (threadIdx.x == 0) red[0] = t;
    }
    __syncthreads();
    float r = red[0];
    __syncthreads();
    return r;
}

// ---------------- LayerNorm: one block per token row ----------------
__global__ void __launch_bounds__(256) ln_kernel(
    const float* __restrict__ x, const float* __restrict__ gw,
    const float* __restrict__ bw, float* __restrict__ out)
{
    __shared__ float red[32];
    const int row = blockIdx.x;
    const float* xr = x + (size_t)row * EMB;

    float vals[3];
    float lsum = 0.0f;
    #pragma unroll
    for (int i = 0; i < 3; i++) {
        vals[i] = xr[threadIdx.x + i * 256];
        lsum += vals[i];
    }
    float mu = block_reduce_sum(lsum, red) * (1.0f / EMB);

    float ls2 = 0.0f;
    #pragma unroll
    for (int i = 0; i < 3; i++) {
        float d = vals[i] - mu;
        ls2 += d * d;
    }
    float var = block_reduce_sum(ls2, red) * (1.0f / EMB);
    float rs = rsqrtf(var + 1e-5f);

    float* outr = out + (size_t)row * EMB;
    #pragma unroll
    for (int i = 0; i < 3; i++) {
        int c = threadIdx.x + i * 256;
        outr[c] = (vals[i] - mu) * rs * gw[c] + bw[c];
    }
}

// ---------------- SGEMM: C[M,N] = A[M,K] @ B[K,N] + bias (+gelu / +residual) ----------------
// BM=BN=128, BK=16, 256 threads, 8x8 per thread.
template<bool GELU, bool RESID>
__global__ void __launch_bounds__(256) sgemm_kernel(
    const float* __restrict__ A, const float* __restrict__ B,
    const float* __restrict__ bias, const float* __restrict__ R,
    float* __restrict__ C, int M, int N, int K)
{
    constexpr int BM = 128, BN = 128, BK = 16;
    __shared__ float As[BK * BM];
    __shared__ float Bs[BK * BN];

    const int tid = threadIdx.x;
    const int bm = blockIdx.y * BM;
    const int bn = blockIdx.x * BN;
    const int tx = tid & 15;
    const int ty = tid >> 4;

    float acc[8][8];
    #pragma unroll
    for (int i = 0; i < 8; i++)
        #pragma unroll
        for (int j = 0; j < 8; j++) acc[i][j] = 0.0f;

    const float* Ap = A + (size_t)bm * K;
    const float* Bp = B + bn;

    for (int k0 = 0; k0 < K; k0 += BK) {
        // load A tile (BM x BK), store transposed As[k][m]
        #pragma unroll
        for (int i = 0; i < 2; i++) {
            int idx = tid + i * 256;          // 512 float4s total
            int r = idx >> 2;                 // 0..127
            int kc = (idx & 3) * 4;           // 0,4,8,12
            float4 va = *(const float4*)(Ap + (size_t)r * K + k0 + kc);
            As[(kc + 0) * BM + r] = va.x;
            As[(kc + 1) * BM + r] = va.y;
            As[(kc + 2) * BM + r] = va.z;
            As[(kc + 3) * BM + r] = va.w;
        }
        // load B tile (BK x BN)
        #pragma unroll
        for (int i = 0; i < 2; i++) {
            int idx = tid + i * 256;
            int r = idx >> 5;                 // 0..15
            int c = (idx & 31) * 4;           // 0..124
            *(float4*)&Bs[r * BN + c] =
                *(const float4*)(Bp + (size_t)(k0 + r) * N + c);
        }
        __syncthreads();

        #pragma unroll
        for (int kk = 0; kk < BK; kk++) {
            float4 a0 = *(const float4*)&As[kk * BM + ty * 8];
            float4 a1 = *(const float4*)&As[kk * BM + ty * 8 + 4];
            float4 b0 = *(const float4*)&Bs[kk * BN + tx * 8];
            float4 b1 = *(const float4*)&Bs[kk * BN + tx * 8 + 4];
            float a[8] = {a0.x, a0.y, a0.z, a0.w, a1.x, a1.y, a1.z, a1.w};
            float b[8] = {b0.x, b0.y, b0.z, b0.w, b1.x, b1.y, b1.z, b1.w};
            #pragma unroll
            for (int i = 0; i < 8; i++)
                #pragma unroll
                for (int j = 0; j < 8; j++)
                    acc[i][j] = fmaf(a[i], b[j], acc[i][j]);
        }
        __syncthreads();
    }

    // epilogue
    float bregs[8];
    #pragma unroll
    for (int j = 0; j < 8; j++) bregs[j] = bias[bn + tx * 8 + j];

    #pragma unroll
    for (int i = 0; i < 8; i++) {
        int m = bm + ty * 8 + i;
        size_t off = (size_t)m * N + bn + tx * 8;
        float o[8];
        #pragma unroll
        for (int j = 0; j < 8; j++) {
            float v = acc[i][j] + bregs[j];
            if (GELU) v = 0.5f * v * (1.0f + erff(v * 0.70710678118654752f));
            o[j] = v;
        }
        if (RESID) {
            float4 r0 = *(const float4*)(R + off);
            float4 r1 = *(const float4*)(R + off + 4);
            o[0] += r0.x; o[1] += r0.y; o[2] += r0.z; o[3] += r0.w;
            o[4] += r1.x; o[5] += r1.y; o[6] += r1.z; o[7] += r1.w;
        }
        *(float4*)(C + off)     = make_float4(o[0], o[1], o[2], o[3]);
        *(float4*)(C + off + 4) = make_float4(o[4], o[5], o[6], o[7]);
    }
}

// ---------------- Flash-style attention ----------------
// grid: (SEQ/64, BATCH*HEADS), 256 threads. Each block: 64-query tile for one (b,h).
// Thread layout: row = tid/4 (query row in tile), g = tid%4 (owns dims g*16..g*16+15).
#define QT 64
#define LDP 65   // padded row length in smem
__global__ void __launch_bounds__(256) attn_kernel(
    const float* __restrict__ q, const float* __restrict__ k,
    const float* __restrict__ v, float* __restrict__ ctx)
{
    extern __shared__ float sm[];
    float* Qs = sm;
    float* Ks = Qs + QT * LDP;
    float* Vs = Ks + QT * LDP;
    float* Ss = Vs + QT * LDP;

    const int qt = blockIdx.x;
    const int bh = blockIdx.y;
    const int b = bh / HEADS;
    const int h = bh % HEADS;
    const int tid = threadIdx.x;
    const int row = tid >> 2;
    const int g = tid & 3;
    const float scale = 0.125f; // 1/sqrt(64)

    // load Q tile (scaled)
    const float* qb = q + ((size_t)(b * SEQ + qt * QT)) * EMB + h * HD;
    #pragma unroll
    for (int i = 0; i < 4; i++) {
        int f = tid + i * 256;       // 1024 float4s
        int r = f >> 4;              // 0..63
        int c = (f & 15) * 4;        // 0..60
        float4 val = *(const float4*)(qb + (size_t)r * EMB + c);
        Qs[r * LDP + c + 0] = val.x * scale;
        Qs[r * LDP + c + 1] = val.y * scale;
        Qs[r * LDP + c + 2] = val.z * scale;
        Qs[r * LDP + c + 3] = val.w * scale;
    }

    float m = -1e30f, l = 0.0f;
    float O[16];
    #pragma unroll
    for (int i = 0; i < 16; i++) O[i] = 0.0f;

    for (int kt = 0; kt < SEQ / QT; kt++) {
        const float* kb = k + ((size_t)(b * SEQ + kt * QT)) * EMB + h * HD;
        const float* vb = v + ((size_t)(b * SEQ + kt * QT)) * EMB + h * HD;
        #pragma unroll
        for (int i = 0; i < 4; i++) {
            int f = tid + i * 256;
            int r = f >> 4;
            int c = (f & 15) * 4;
            float4 kv = *(const float4*)(kb + (size_t)r * EMB + c);
            Ks[r * LDP + c + 0] = kv.x; Ks[r * LDP + c + 1] = kv.y;
            Ks[r * LDP + c + 2] = kv.z; Ks[r * LDP + c + 3] = kv.w;
            float4 vv = *(const float4*)(vb + (size_t)r * EMB + c);
            Vs[r * LDP + c + 0] = vv.x; Vs[r * LDP + c + 1] = vv.y;
            Vs[r * LDP + c + 2] = vv.z; Vs[r * LDP + c + 3] = vv.w;
        }
        __syncthreads();

        // S = Qs(row) . Ks(kj), 16 kj per thread
        float s[16];
        #pragma unroll
        for (int i = 0; i < 16; i++) s[i] = 0.0f;
        for (int d = 0; d < HD; d++) {
            float qv = Qs[row * LDP + d];
            #pragma unroll
            for (int i = 0; i < 16; i++)
                s[i] = fmaf(qv, Ks[(g * 16 + i) * LDP + d], s[i]);
        }

        // online softmax update (group of 4 threads shares a row)
        float tmax = s[0];
        #pragma unroll
        for (int i = 1; i < 16; i++) tmax = fmaxf(tmax, s[i]);
        tmax = fmaxf(tmax, __shfl_xor_sync(0xffffffffu, tmax, 1));
        tmax = fmaxf(tmax, __shfl_xor_sync(0xffffffffu, tmax, 2));
        float mnew = fmaxf(m, tmax);
        float alpha = __expf(m - mnew);

        float psum = 0.0f;
        #pragma unroll
        for (int i = 0; i < 16; i++) {
            float p = __expf(s[i] - mnew);
            psum += p;
            Ss[row * LDP + g * 16 + i] = p;
        }
        psum += __shfl_xor_sync(0xffffffffu, psum, 1);
        psum += __shfl_xor_sync(0xffffffffu, psum, 2);
        l = l * alpha + psum;
        m = mnew;
        #pragma unroll
        for (int i = 0; i < 16; i++) O[i] *= alpha;
        __syncthreads();

        // O += P @ V
        for (int kj = 0; kj < QT; kj++) {
            float pv = Ss[row * LDP + kj];
            #pragma unroll
            for (int i = 0; i < 16; i++)
                O[i] = fmaf(pv, Vs[kj * LDP + g * 16 + i], O[i]);
        }
        __syncthreads();
    }

    float inv = 1.0f / l;
    float* outp = ctx + ((size_t)(b * SEQ + qt * QT + row)) * EMB + h * HD + g * 16;
    #pragma unroll
    for (int i = 0; i < 16; i++) outp[i] = O[i] * inv;
}

// ---------------- launch ----------------
extern "C" void kernel_launch(void* const* d_in, const int* in_sizes, int n_in,
                              void* d_out, int out_size)
{
    const float* x     = (const float*)d_in[0];
    const float* ln1_g = (const float*)d_in[1];
    const float* ln1_b = (const float*)d_in[2];
    const float* Wq    = (const float*)d_in[3];
    const float* bq    = (const float*)d_in[4];
    const float* Wk    = (const float*)d_in[5];
    const float* bk    = (const float*)d_in[6];
    const float* Wv    = (const float*)d_in[7];
    const float* bv    = (const float*)d_in[8];
    const float* Wo    = (const float*)d_in[9];
    const float* bo    = (const float*)d_in[10];
    const float* ln2_g = (const float*)d_in[11];
    const float* ln2_b = (const float*)d_in[12];
    const float* W1    = (const float*)d_in[13];
    const float* b1    = (const float*)d_in[14];
    const float* W2    = (const float*)d_in[15];
    const float* b2    = (const float*)d_in[16];
    float* out = (float*)d_out;

    float *h, *q, *k, *v, *ctx, *x1, *h2, *ff;
    cudaGetSymbolAddress((void**)&h,   g_h);
    cudaGetSymbolAddress((void**)&q,   g_q);
    cudaGetSymbolAddress((void**)&k,   g_k);
    cudaGetSymbolAddress((void**)&v,   g_v);
    cudaGetSymbolAddress((void**)&ctx, g_ctx);
    cudaGetSymbolAddress((void**)&x1,  g_x1);
    cudaGetSymbolAddress((void**)&h2,  g_h2);
    cudaGetSymbolAddress((void**)&ff,  g_ff);

    const int smem_attn = 4 * QT * LDP * sizeof(float); // 66560 B
    cudaFuncSetAttribute(attn_kernel,
                         cudaFuncAttributeMaxDynamicSharedMemorySize, smem_attn);

    dim3 g768(EMB / 128, NTOK / 128);
    dim3 g3072(DFF / 128, NTOK / 128);

    // 1. LN1
    ln_kernel<<<NTOK, 256>>>(x, ln1_g, ln1_b, h);
    // 2-4. QKV projections
    sgemm_kernel<false, false><<<g768, 256>>>(h, Wq, bq, nullptr, q, NTOK, EMB, EMB);
    sgemm_kernel<false, false><<<g768, 256>>>(h, Wk, bk, nullptr, k, NTOK, EMB, EMB);
    sgemm_kernel<false, false><<<g768, 256>>>(h, Wv, bv, nullptr, v, NTOK, EMB, EMB);
    // 5. attention
    attn_kernel<<<dim3(SEQ / QT, BATCH * HEADS), 256, smem_attn>>>(q, k, v, ctx);
    // 6. output projection + residual
    sgemm_kernel<false, true><<<g768, 256>>>(ctx, Wo, bo, x, x1, NTOK, EMB, EMB);
    // 7. LN2
    ln_kernel<<<NTOK, 256>>>(x1, ln2_g, ln2_b, h2);
    // 8. FFN up + GELU
    sgemm_kernel<true, false><<<g3072, 256>>>(h2, W1, b1, nullptr, ff, NTOK, DFF, EMB);
    // 9. FFN down + residual -> output
    sgemm_kernel<false, true><<<g768, 256>>>(ff, W2, b2, x1, out, NTOK, EMB, DFF);
}

// round 2
// speedup vs baseline: 3.5824x; 3.5824x over previous
#include <cuda_runtime.h>
#include <math.h>

#define EMB   768
#define DFF   3072
#define NTOK  16384
#define HEADS 12
#define HD    64
#define SEQ   1024
#define BATCH 16

// ---------------- scratch (no allocations allowed) ----------------
__device__ float g_h  [NTOK * EMB];
__device__ float g_q  [NTOK * EMB];
__device__ float g_k  [NTOK * EMB];
__device__ float g_v  [NTOK * EMB];
__device__ float g_ctx[NTOK * EMB];
__device__ float g_x1 [NTOK * EMB];
__device__ float g_h2 [NTOK * EMB];
__device__ float g_ff [NTOK * DFF];
__device__ float g_s  [(size_t)BATCH * HEADS * SEQ * SEQ];   // 805 MB attention scores

// ---------------- helpers ----------------
__device__ __forceinline__ unsigned f2tf(float f) {
    unsigned u;
    asm("cvt.rna.tf32.f32 %0, %1;" : "=r"(u) : "f"(f));
    return u;
}

__device__ __forceinline__ void mma8(float* c, const unsigned* a, const unsigned* b) {
    asm volatile(
        "mma.sync.aligned.m16n8k8.row.col.f32.tf32.tf32.f32 "
        "{%0,%1,%2,%3}, {%4,%5,%6,%7}, {%8,%9}, {%0,%1,%2,%3};"
        : "+f"(c[0]), "+f"(c[1]), "+f"(c[2]), "+f"(c[3])
        : "r"(a[0]), "r"(a[1]), "r"(a[2]), "r"(a[3]), "r"(b[0]), "r"(b[1]));
}

__device__ __forceinline__ float block_reduce_sum(float v, float* red) {
    #pragma unroll
    for (int off = 16; off > 0; off >>= 1)
        v += __shfl_xor_sync(0xffffffffu, v, off);
    int w = threadIdx.x >> 5;
    if ((threadIdx.x & 31) == 0) red[w] = v;
    __syncthreads();
    if (threadIdx.x < 32) {
        float t = (threadIdx.x < 8) ? red[threadIdx.x] : 0.0f;
        #pragma unroll
        for (int off = 4; off > 0; off >>= 1)
            t += __shfl_xor_sync(0xffffffffu, t, off);
        if (threadIdx.x == 0) red[0] = t;
    }
    __syncthreads();
    float r = red[0];
    __syncthreads();
    return r;
}

__device__ __forceinline__ float block_reduce_max(float v, float* red) {
    #pragma unroll
    for (int off = 16; off > 0; off >>= 1)
        v = fmaxf(v, __shfl_xor_sync(0xffffffffu, v, off));
    int w = threadIdx.x >> 5;
    if ((threadIdx.x & 31) == 0) red[w] = v;
    __syncthreads();
    if (threadIdx.x < 32) {
        float t = (threadIdx.x < 8) ? red[threadIdx.x] : -1e30f;
        #pragma unroll
        for (int off = 4; off > 0; off >>= 1)
            t = fmaxf(t, __shfl_xor_sync(0xffffffffu, t, off));
        if (threadIdx.x == 0) red[0] = t;
    }
    __syncthreads();
    float r = red[0];
    __syncthreads();
    return r;
}

// ---------------- LayerNorm: one block per token row ----------------
__global__ void __launch_bounds__(256) ln_kernel(
    const float* __restrict__ x, const float* __restrict__ gw,
    const float* __restrict__ bw, float* __restrict__ out)
{
    __shared__ float red[32];
    const int row = blockIdx.x;
    const float* xr = x + (size_t)row * EMB;

    float vals[3];
    float lsum = 0.0f;
    #pragma unroll
    for (int i = 0; i < 3; i++) {
        vals[i] = xr[threadIdx.x + i * 256];
        lsum += vals[i];
    }
    float mu = block_reduce_sum(lsum, red) * (1.0f / EMB);

    float ls2 = 0.0f;
    #pragma unroll
    for (int i = 0; i < 3; i++) {
        float d = vals[i] - mu;
        ls2 += d * d;
    }
    float var = block_reduce_sum(ls2, red) * (1.0f / EMB);
    float rs = rsqrtf(var + 1e-5f);

    float* outr = out + (size_t)row * EMB;
    #pragma unroll
    for (int i = 0; i < 3; i++) {
        int c = threadIdx.x + i * 256;
        outr[c] = (vals[i] - mu) * rs * gw[c] + bw[c];
    }
}

// ---------------- row softmax over S (rows of length SEQ) ----------------
__global__ void __launch_bounds__(256) softmax_kernel(float* __restrict__ S)
{
    __shared__ float red[32];
    float* row = S + ((size_t)blockIdx.y * SEQ + blockIdx.x) * SEQ;
    float4 v = ((float4*)row)[threadIdx.x];
    float m = fmaxf(fmaxf(v.x, v.y), fmaxf(v.z, v.w));
    m = block_reduce_max(m, red);
    v.x = __expf(v.x - m); v.y = __expf(v.y - m);
    v.z = __expf(v.z - m); v.w = __expf(v.w - m);
    float s = v.x + v.y + v.z + v.w;
    s = block_reduce_sum(s, red);
    float inv = 1.0f / s;
    v.x *= inv; v.y *= inv; v.z *= inv; v.w *= inv;
    ((float4*)row)[threadIdx.x] = v;
}

// ---------------- tf32 tensor-core GEMM ----------------
// C[M,N] = scale * (A @ B or A @ B^T) (+bias)(+gelu)(+residual)
// MODE 0: plain GEMM, strides lda/ldb/ldc, grid (N/BN, M/BM, 1)
// MODE 1: batched QK^T per (b,h): A=Q, B=K (both [tok, EMB] with head offset),
//         C = S + z*SEQ*SEQ, grid.z = BATCH*HEADS
// MODE 2: batched P@V per (b,h): A = S + z*SEQ*SEQ, B = V (head offset),
//         C = ctx (head offset)
template<int BM, int BN, int BK, int WM, int WN, int MODE,
         bool TRANSB, bool DO_GELU, bool DO_RESID>
__global__ void __launch_bounds__(256) mma_gemm(
    const float* __restrict__ A, const float* __restrict__ B,
    const float* __restrict__ bias, const float* __restrict__ R,
    float* __restrict__ C, int M, int N, int K,
    int lda, int ldb, int ldc, float scale)
{
    constexpr int BMP = BM + 8;
    constexpr int BNP = BN + 8;
    constexpr int MT = WM / 16;
    constexpr int NT = WN / 8;
    constexpr int WARPS_N = BN / WN;

    __shared__ unsigned As[BK * BMP];
    __shared__ unsigned Bs[BK * BNP];

    const int tid  = threadIdx.x;
    const int w    = tid >> 5;
    const int lane = tid & 31;
    const int gi   = lane >> 2;
    const int li   = lane & 3;
    const int wn   = w % WARPS_N;
    const int wm   = w / WARPS_N;
    const int bm   = blockIdx.y * BM;
    const int bn   = blockIdx.x * BN;

    const float* Ab = A;
    const float* Bb = B;
    float*       Cb = C;
    const float* Rb = R;
    if (MODE == 1) {
        int z = blockIdx.z, b = z / HEADS, h = z % HEADS;
        Ab = A + (size_t)b * SEQ * lda + h * HD;
        Bb = B + (size_t)b * SEQ * ldb + h * HD;
        Cb = C + (size_t)z * SEQ * SEQ;
    } else if (MODE == 2) {
        int z = blockIdx.z, b = z / HEADS, h = z % HEADS;
        Ab = A + (size_t)z * SEQ * SEQ;
        Bb = B + (size_t)b * SEQ * ldb + h * HD;
        Cb = C + (size_t)b * SEQ * ldc + h * HD;
    }

    float acc[MT][NT][4];
    #pragma unroll
    for (int i = 0; i < MT; i++)
        #pragma unroll
        for (int j = 0; j < NT; j++)
            #pragma unroll
            for (int t = 0; t < 4; t++) acc[i][j][t] = 0.0f;

    for (int k0 = 0; k0 < K; k0 += BK) {
        // ---- A tile: BM x BK, store k-major As[k][m] ----
        #pragma unroll
        for (int i = 0; i < (BM * BK) / 1024; i++) {
            int idx = tid + i * 256;
            int r  = idx >> 2;
            int kc = (idx & 3) * 4;
            float4 va = *(const float4*)(Ab + (size_t)(bm + r) * lda + k0 + kc);
            As[(kc + 0) * BMP + r] = f2tf(va.x);
            As[(kc + 1) * BMP + r] = f2tf(va.y);
            As[(kc + 2) * BMP + r] = f2tf(va.z);
            As[(kc + 3) * BMP + r] = f2tf(va.w);
        }
        // ---- B tile ----
        if (TRANSB) {
            // B is [N,K] row-major; tile BN x BK, store k-major Bs[k][n]
            #pragma unroll
            for (int i = 0; i < (BN * BK) / 1024; i++) {
                int idx = tid + i * 256;
                int r  = idx >> 2;
                int kc = (idx & 3) * 4;
                float4 vb = *(const float4*)(Bb + (size_t)(bn + r) * ldb + k0 + kc);
                Bs[(kc + 0) * BNP + r] = f2tf(vb.x);
                Bs[(kc + 1) * BNP + r] = f2tf(vb.y);
                Bs[(kc + 2) * BNP + r] = f2tf(vb.z);
                Bs[(kc + 3) * BNP + r] = f2tf(vb.w);
            }
        } else {
            // B is [K,N] row-major; tile BK x BN
            #pragma unroll
            for (int i = 0; i < (BK * BN) / 1024; i++) {
                int idx = tid + i * 256;
                int r = idx / (BN / 4);
                int c = (idx % (BN / 4)) * 4;
                float4 vb = *(const float4*)(Bb + (size_t)(k0 + r) * ldb + bn + c);
                Bs[r * BNP + c + 0] = f2tf(vb.x);
                Bs[r * BNP + c + 1] = f2tf(vb.y);
                Bs[r * BNP + c + 2] = f2tf(vb.z);
                Bs[r * BNP + c + 3] = f2tf(vb.w);
            }
        }
        __syncthreads();

        #pragma unroll
        for (int ks = 0; ks < BK / 8; ks++) {
            const int kb = ks * 8;
            unsigned af[MT][4];
            #pragma unroll
            for (int mt = 0; mt < MT; mt++) {
                int r0 = wm * WM + mt * 16 + gi;
                af[mt][0] = As[(kb + li) * BMP + r0];
                af[mt][1] = As[(kb + li) * BMP + r0 + 8];
                af[mt][2] = As[(kb + li + 4) * BMP + r0];
                af[mt][3] = As[(kb + li + 4) * BMP + r0 + 8];
            }
            unsigned bf[NT][2];
            #pragma unroll
            for (int nt = 0; nt < NT; nt++) {
                int c0 = wn * WN + nt * 8 + gi;
                bf[nt][0] = Bs[(kb + li) * BNP + c0];
                bf[nt][1] = Bs[(kb + li + 4) * BNP + c0];
            }
            #pragma unroll
            for (int mt = 0; mt < MT; mt++)
                #pragma unroll
                for (int nt = 0; nt < NT; nt++)
                    mma8(acc[mt][nt], af[mt], bf[nt]);
        }
        __syncthreads();
    }

    // ---- epilogue ----
    #pragma unroll
    for (int mt = 0; mt < MT; mt++) {
        #pragma unroll
        for (int nt = 0; nt < NT; nt++) {
            int row = bm + wm * WM + mt * 16 + gi;
            int col = bn + wn * WN + nt * 8 + 2 * li;
            float bi0 = 0.0f, bi1 = 0.0f;
            if (bias) { bi0 = bias[col]; bi1 = bias[col + 1]; }
            #pragma unroll
            for (int half = 0; half < 2; half++) {
                int rr = row + half * 8;
                float v0 = acc[mt][nt][half * 2 + 0] * scale + bi0;
                float v1 = acc[mt][nt][half * 2 + 1] * scale + bi1;
                if (DO_GELU) {
                    v0 = 0.5f * v0 * (1.0f + erff(v0 * 0.70710678118654752f));
                    v1 = 0.5f * v1 * (1.0f + erff(v1 * 0.70710678118654752f));
                }
                if (DO_RESID) {
                    float2 r2 = *(const float2*)(Rb + (size_t)rr * ldc + col);
                    v0 += r2.x; v1 += r2.y;
                }
                *(float2*)(Cb + (size_t)rr * ldc + col) = make_float2(v0, v1);
            }
        }
    }
}

// ---------------- launch ----------------
extern "C" void kernel_launch(void* const* d_in, const int* in_sizes, int n_in,
                              void* d_out, int out_size)
{
    const float* x     = (const float*)d_in[0];
    const float* ln1_g = (const float*)d_in[1];
    const float* ln1_b = (const float*)d_in[2];
    const float* Wq    = (const float*)d_in[3];
    const float* bq    = (const float*)d_in[4];
    const float* Wk    = (const float*)d_in[5];
    const float* bk    = (const float*)d_in[6];
    const float* Wv    = (const float*)d_in[7];
    const float* bv    = (const float*)d_in[8];
    const float* Wo    = (const float*)d_in[9];
    const float* bo    = (const float*)d_in[10];
    const float* ln2_g = (const float*)d_in[11];
    const float* ln2_b = (const float*)d_in[12];
    const float* W1    = (const float*)d_in[13];
    const float* b1    = (const float*)d_in[14];
    const float* W2    = (const float*)d_in[15];
    const float* b2    = (const float*)d_in[16];
    float* out = (float*)d_out;

    float *h, *q, *k, *v, *ctx, *x1, *h2, *ff, *s;
    cudaGetSymbolAddress((void**)&h,   g_h);
    cudaGetSymbolAddress((void**)&q,   g_q);
    cudaGetSymbolAddress((void**)&k,   g_k);
    cudaGetSymbolAddress((void**)&v,   g_v);
    cudaGetSymbolAddress((void**)&ctx, g_ctx);
    cudaGetSymbolAddress((void**)&x1,  g_x1);
    cudaGetSymbolAddress((void**)&h2,  g_h2);
    cudaGetSymbolAddress((void**)&ff,  g_ff);
    cudaGetSymbolAddress((void**)&s,   g_s);

    dim3 g768(EMB / 128, NTOK / 128);    // (6, 128)
    dim3 g3072(DFF / 128, NTOK / 128);   // (24, 128)
    dim3 gqkt(SEQ / 128, SEQ / 128, BATCH * HEADS);   // (8, 8, 192)
    dim3 gpv(1, SEQ / 128, BATCH * HEADS);            // (1, 8, 192)
    dim3 gsm(SEQ, BATCH * HEADS);                     // softmax rows

    // 1. LN1
    ln_kernel<<<NTOK, 256>>>(x, ln1_g, ln1_b, h);

    // 2-4. QKV projections: [16384,768] @ [768,768] + bias
    mma_gemm<128,128,16,64,32,0,false,false,false><<<g768, 256>>>(
        h, Wq, bq, nullptr, q, NTOK, EMB, EMB, EMB, EMB, EMB, 1.0f);
    mma_gemm<128,128,16,64,32,0,false,false,false><<<g768, 256>>>(
        h, Wk, bk, nullptr, k, NTOK, EMB, EMB, EMB, EMB, EMB, 1.0f);
    mma_gemm<128,128,16,64,32,0,false,false,false><<<g768, 256>>>(
        h, Wv, bv, nullptr, v, NTOK, EMB, EMB, EMB, EMB, EMB, 1.0f);

    // 5. S = scale * Q K^T  (batched over b,h; TRANSB)
    mma_gemm<128,128,16,64,32,1,true,false,false><<<gqkt, 256>>>(
        q, k, nullptr, nullptr, s, SEQ, SEQ, HD, EMB, EMB, SEQ, 0.125f);

    // 6. softmax rows of S
    softmax_kernel<<<gsm, 256>>>(s);

    // 7. ctx = P @ V (batched)
    mma_gemm<128,64,16,32,32,2,false,false,false><<<gpv, 256>>>(
        s, v, nullptr, nullptr, ctx, SEQ, HD, SEQ, SEQ, EMB, EMB, 1.0f);

    // 8. x1 = ctx @ Wo + bo + x
    mma_gemm<128,128,16,64,32,0,false,false,true><<<g768, 256>>>(
        ctx, Wo, bo, x, x1, NTOK, EMB, EMB, EMB, EMB, EMB, 1.0f);

    // 9. LN2
    ln_kernel<<<NTOK, 256>>>(x1, ln2_g, ln2_b, h2);

    // 10. ff = gelu(h2 @ W1 + b1)
    mma_gemm<128,128,16,64,32,0,false,true,false><<<g3072, 256>>>(
        h2, W1, b1, nullptr, ff, NTOK, DFF, EMB, EMB, DFF, DFF, 1.0f);

    // 11. out = ff @ W2 + b2 + x1
    mma_gemm<128,128,16,64,32,0,false,false,true><<<g768, 256>>>(
        ff, W2, b2, x1, out, NTOK, EMB, DFF, DFF, EMB, EMB, 1.0f);
}

// round 3
// speedup vs baseline: 5.0211x; 1.4016x over previous
#include <cuda_runtime.h>
#include <math.h>
#include <stdint.h>

#define EMB   768
#define DFF   3072
#define NTOK  16384
#define HEADS 12
#define HD    64
#define SEQ   1024
#define BATCH 16
#define QKV3  2304

// ---------------- scratch (no allocations allowed) ----------------
__device__ float g_h   [NTOK * EMB];
__device__ float g_qkv [NTOK * QKV3];
__device__ float g_vt  [(size_t)BATCH * HEADS * HD * SEQ];
__device__ float g_ctx [NTOK * EMB];
__device__ float g_x1  [NTOK * EMB];
__device__ float g_h2  [NTOK * EMB];
__device__ float g_ff  [NTOK * DFF];
__device__ float g_s   [(size_t)BATCH * HEADS * SEQ * SEQ];
// pre-transposed + tf32-rounded weights
__device__ float g_wqkvT[QKV3 * EMB];
__device__ float g_woT  [EMB * EMB];
__device__ float g_w1T  [DFF * EMB];
__device__ float g_w2T  [EMB * DFF];
__device__ float g_bqkv [QKV3];

// ---------------- helpers ----------------
__device__ __forceinline__ float f2tf(float f) {
    unsigned u;
    asm("cvt.rna.tf32.f32 %0, %1;" : "=r"(u) : "f"(f));
    return __uint_as_float(u);
}

__device__ __forceinline__ void mma8(float* c, const unsigned* a, const unsigned* b) {
    asm volatile(
        "mma.sync.aligned.m16n8k8.row.col.f32.tf32.tf32.f32 "
        "{%0,%1,%2,%3}, {%4,%5,%6,%7}, {%8,%9}, {%0,%1,%2,%3};"
        : "+f"(c[0]), "+f"(c[1]), "+f"(c[2]), "+f"(c[3])
        : "r"(a[0]), "r"(a[1]), "r"(a[2]), "r"(a[3]), "r"(b[0]), "r"(b[1]));
}

__device__ __forceinline__ void ldsm4(unsigned& r0, unsigned& r1, unsigned& r2,
                                      unsigned& r3, uint32_t addr) {
    asm volatile("ldmatrix.sync.aligned.m8n8.x4.shared.b16 {%0,%1,%2,%3}, [%4];"
                 : "=r"(r0), "=r"(r1), "=r"(r2), "=r"(r3) : "r"(addr));
}

#define CP_ASYNC16(dst, src) \
    asm volatile("cp.async.cg.shared.global [%0], [%1], 16;" :: "r"(dst), "l"(src))
#define CP_COMMIT() asm volatile("cp.async.commit_group;")
#define CP_WAIT1()  asm volatile("cp.async.wait_group 1;")

__device__ __forceinline__ float block_reduce_sum(float v, float* red) {
    #pragma unroll
    for (int off = 16; off > 0; off >>= 1)
        v += __shfl_xor_sync(0xffffffffu, v, off);
    int w = threadIdx.x >> 5;
    if ((threadIdx.x & 31) == 0) red[w] = v;
    __syncthreads();
    if (threadIdx.x < 32) {
        float t = (threadIdx.x < 8) ? red[threadIdx.x] : 0.0f;
        #pragma unroll
        for (int off = 4; off > 0; off >>= 1)
            t += __shfl_xor_sync(0xffffffffu, t, off);
        if (threadIdx.x == 0) red[0] = t;
    }
    __syncthreads();
    float r = red[0];
    __syncthreads();
    return r;
}

__device__ __forceinline__ float block_reduce_max(float v, float* red) {
    #pragma unroll
    for (int off = 16; off > 0; off >>= 1)
        v = fmaxf(v, __shfl_xor_sync(0xffffffffu, v, off));
    int w = threadIdx.x >> 5;
    if ((threadIdx.x & 31) == 0) red[w] = v;
    __syncthreads();
    if (threadIdx.x < 32) {
        float t = (threadIdx.x < 8) ? red[threadIdx.x] : -1e30f;
        #pragma unroll
        for (int off = 4; off > 0; off >>= 1)
            t = fmaxf(t, __shfl_xor_sync(0xffffffffu, t, off));
        if (threadIdx.x == 0) red[0] = t;
    }
    __syncthreads();
    float r = red[0];
    __syncthreads();
    return r;
}

// ---------------- prep kernels ----------------
__global__ void __launch_bounds__(256) transpose_rna(
    const float* __restrict__ src, float* __restrict__ dst, int K, int N)
{
    __shared__ float t[32][33];
    const int n0 = blockIdx.x * 32;
    const int k0 = blockIdx.y * 32;
    const int tx = threadIdx.x & 31;
    const int ty = threadIdx.x >> 5;
    #pragma unroll
    for (int j = 0; j < 4; j++)
        t[ty + j * 8][tx] = src[(size_t)(k0 + ty + j * 8) * N + n0 + tx];
    __syncthreads();
    #pragma unroll
    for (int j = 0; j < 4; j++)
        dst[(size_t)(n0 + ty + j * 8) * K + k0 + tx] = f2tf(t[tx][ty + j * 8]);
}

__global__ void bias_concat(const float* bq, const float* bk, const float* bv,
                            float* out)
{
    int i = blockIdx.x * 256 + threadIdx.x;
    if (i < QKV3) {
        float v = (i < EMB) ? bq[i] : (i < 2 * EMB) ? bk[i - EMB] : bv[i - 2 * EMB];
        out[i] = v;
    }
}

__global__ void __launch_bounds__(256) v_transpose(
    const float* __restrict__ qkv, float* __restrict__ vt)
{
    __shared__ float t[32][33];
    const int z = blockIdx.z;
    const int b = z / HEADS, h = z % HEADS;
    const int t0 = blockIdx.x * 32;
    const int d0 = blockIdx.y * 32;
    const int tx = threadIdx.x & 31;
    const int ty = threadIdx.x >> 5;
    const float* src = qkv + (size_t)(b * SEQ) * QKV3 + 2 * EMB + h * HD;
    #pragma unroll
    for (int j = 0; j < 4; j++)
        t[ty + j * 8][tx] = src[(size_t)(t0 + ty + j * 8) * QKV3 + d0 + tx];
    __syncthreads();
    float* dst = vt + ((size_t)z * HD) * SEQ;
    #pragma unroll
    for (int j = 0; j < 4; j++)
        dst[(size_t)(d0 + ty + j * 8) * SEQ + t0 + tx] = t[tx][ty + j * 8];
}

// ---------------- LayerNorm (outputs tf32-rounded) ----------------
__global__ void __launch_bounds__(256) ln_kernel(
    const float* __restrict__ x, const float* __restrict__ gw,
    const float* __restrict__ bw, float* __restrict__ out)
{
    __shared__ float red[32];
    const int row = blockIdx.x;
    const float* xr = x + (size_t)row * EMB;

    float vals[3];
    float lsum = 0.0f;
    #pragma unroll
    for (int i = 0; i < 3; i++) {
        vals[i] = xr[threadIdx.x + i * 256];
        lsum += vals[i];
    }
    float mu = block_reduce_sum(lsum, red) * (1.0f / EMB);

    float ls2 = 0.0f;
    #pragma unroll
    for (int i = 0; i < 3; i++) {
        float d = vals[i] - mu;
        ls2 += d * d;
    }
    float var = block_reduce_sum(ls2, red) * (1.0f / EMB);
    float rs = rsqrtf(var + 1e-5f);

    float* outr = out + (size_t)row * EMB;
    #pragma unroll
    for (int i = 0; i < 3; i++) {
        int c = threadIdx.x + i * 256;
        outr[c] = f2tf((vals[i] - mu) * rs * gw[c] + bw[c]);
    }
}

// ---------------- row softmax over S, outputs tf32-rounded P ----------------
__global__ void __launch_bounds__(256) softmax_kernel(float* __restrict__ S)
{
    __shared__ float red[32];
    float* row = S + ((size_t)blockIdx.y * SEQ + blockIdx.x) * SEQ;
    float4 v = ((float4*)row)[threadIdx.x];
    float m = fmaxf(fmaxf(v.x, v.y), fmaxf(v.z, v.w));
    m = block_reduce_max(m, red);
    v.x = __expf(v.x - m); v.y = __expf(v.y - m);
    v.z = __expf(v.z - m); v.w = __expf(v.w - m);
    float s = v.x + v.y + v.z + v.w;
    s = block_reduce_sum(s, red);
    float inv = 1.0f / s;
    v.x = f2tf(v.x * inv); v.y = f2tf(v.y * inv);
    v.z = f2tf(v.z * inv); v.w = f2tf(v.w * inv);
    ((float4*)row)[threadIdx.x] = v;
}

// ---------------- tf32 tensor-core GEMM, cp.async double-buffered, ldmatrix ----
template<int BM, int BN, int WM, int WN, int MODE,
         bool DO_GELU, bool DO_RESID, bool RNA_OUT>
__global__ void __launch_bounds__(256) mma_gemm(
    const float* __restrict__ A, const float* __restrict__ B,
    const float* __restrict__ bias, const float* __restrict__ R,
    float* __restrict__ C, int M, int N, int K,
    int lda, int ldb, int ldc, float scale)
{
    constexpr int BK = 32, BKP = 36;
    constexpr int MT = WM / 16;
    constexpr int NT = WN / 8;
    constexpr int WARPS_N = BN / WN;
    constexpr int STAGE = (BM + BN) * BKP;

    extern __shared__ unsigned smem[];
    const uint32_t base = (uint32_t)__cvta_generic_to_shared(smem);

    const int tid  = threadIdx.x;
    const int w    = tid >> 5;
    const int lane = tid & 31;
    const int gi   = lane >> 2;
    const int li   = lane & 3;
    const int wn   = w % WARPS_N;
    const int wm   = w / WARPS_N;
    const int bm   = blockIdx.y * BM;
    const int bn   = blockIdx.x * BN;

    const float* Ab = A;
    const float* Bb = B;
    float*       Cb = C;
    const float* Rb = R;
    if (MODE == 1) {
        int z = blockIdx.z, b = z / HEADS, h = z % HEADS;
        Ab = A + (size_t)b * SEQ * lda + h * HD;
        Bb = B + (size_t)b * SEQ * ldb + h * HD;
        Cb = C + (size_t)z * SEQ * SEQ;
    } else if (MODE == 2) {
        int z = blockIdx.z, b = z / HEADS, h = z % HEADS;
        Ab = A + (size_t)z * SEQ * SEQ;
        Bb = B + (size_t)z * HD * ldb;
        Cb = C + (size_t)b * SEQ * ldc + h * HD;
    }

    const int rowA = wm * WM + (lane & 15);
    const int kqA  = (lane >> 4) * 4;
    const int rowB = wn * WN + ((lane >> 4) & 1) * 8 + (lane & 7);
    const int kqB  = ((lane >> 3) & 1) * 4;

    auto load_tile = [&](int k0, int st) {
        uint32_t sA = base + (uint32_t)st * STAGE * 4;
        uint32_t sB = sA + BM * BKP * 4;
        #pragma unroll
        for (int i = 0; i < BM / 32; i++) {
            int idx = tid + i * 256;
            int r = idx >> 3, c = (idx & 7) * 4;
            CP_ASYNC16(sA + (uint32_t)(r * BKP + c) * 4,
                       Ab + (size_t)(bm + r) * lda + k0 + c);
        }
        #pragma unroll
        for (int i = 0; i < BN / 32; i++) {
            int idx = tid + i * 256;
            int r = idx >> 3, c = (idx & 7) * 4;
            CP_ASYNC16(sB + (uint32_t)(r * BKP + c) * 4,
                       Bb + (size_t)(bn + r) * ldb + k0 + c);
        }
    };

    float acc[MT][NT][4];
    #pragma unroll
    for (int i = 0; i < MT; i++)
        #pragma unroll
        for (int j = 0; j < NT; j++)
            #pragma unroll
            for (int t = 0; t < 4; t++) acc[i][j][t] = 0.0f;

    const int iters = K / BK;
    load_tile(0, 0);
    CP_COMMIT();

    for (int it = 0; it < iters; ++it) {
        const int st = it & 1;
        if (it + 1 < iters) load_tile((it + 1) * BK, st ^ 1);
        CP_COMMIT();
        CP_WAIT1();
        __syncthreads();

        uint32_t sA = base + (uint32_t)st * STAGE * 4;
        uint32_t sB = sA + BM * BKP * 4;

        #pragma unroll
        for (int ks = 0; ks < BK / 8; ks++) {
            const int kb = ks * 8;
            unsigned af[MT][4];
            #pragma unroll
            for (int mt = 0; mt < MT; mt++) {
                uint32_t ad = sA + (uint32_t)((rowA + mt * 16) * BKP + kb + kqA) * 4;
                ldsm4(af[mt][0], af[mt][1], af[mt][2], af[mt][3], ad);
            }
            unsigned bf[NT][2];
            #pragma unroll
            for (int p = 0; p < NT / 2; p++) {
                uint32_t ad = sB + (uint32_t)((rowB + p * 16) * BKP + kb + kqB) * 4;
                unsigned r0, r1, r2, r3;
                ldsm4(r0, r1, r2, r3, ad);
                bf[2 * p][0] = r0; bf[2 * p][1] = r1;
                bf[2 * p + 1][0] = r2; bf[2 * p + 1][1] = r3;
            }
            #pragma unroll
            for (int mt = 0; mt < MT; mt++)
                #pragma unroll
                for (int nt = 0; nt < NT; nt++)
                    mma8(acc[mt][nt], af[mt], bf[nt]);
        }
        __syncthreads();
    }

    #pragma unroll
    for (int mt = 0; mt < MT; mt++) {
        #pragma unroll
        for (int nt = 0; nt < NT; nt++) {
            int row = bm + wm * WM + mt * 16 + gi;
            int col = bn + wn * WN + nt * 8 + 2 * li;
            float bi0 = 0.0f, bi1 = 0.0f;
            if (bias) { bi0 = bias[col]; bi1 = bias[col + 1]; }
            #pragma unroll
            for (int half = 0; half < 2; half++) {
                int rr = row + half * 8;
                float v0 = acc[mt][nt][half * 2 + 0] * scale + bi0;
                float v1 = acc[mt][nt][half * 2 + 1] * scale + bi1;
                if (DO_GELU) {
                    v0 = 0.5f * v0 * (1.0f + erff(v0 * 0.70710678118654752f));
                    v1 = 0.5f * v1 * (1.0f + erff(v1 * 0.70710678118654752f));
                }
                if (DO_RESID) {
                    float2 r2 = *(const float2*)(Rb + (size_t)rr * ldc + col);
                    v0 += r2.x; v1 += r2.y;
                }
                if (RNA_OUT) { v0 = f2tf(v0); v1 = f2tf(v1); }
                *(float2*)(Cb + (size_t)rr * ldc + col) = make_float2(v0, v1);
            }
        }
    }
}

// ---------------- launch ----------------
extern "C" void kernel_launch(void* const* d_in, const int* in_sizes, int n_in,
                              void* d_out, int out_size)
{
    const float* x     = (const float*)d_in[0];
    const float* ln1_g = (const float*)d_in[1];
    const float* ln1_b = (const float*)d_in[2];
    const float* Wq    = (const float*)d_in[3];
    const float* bq    = (const float*)d_in[4];
    const float* Wk    = (const float*)d_in[5];
    const float* bk    = (const float*)d_in[6];
    const float* Wv    = (const float*)d_in[7];
    const float* bv    = (const float*)d_in[8];
    const float* Wo    = (const float*)d_in[9];
    const float* bo    = (const float*)d_in[10];
    const float* ln2_g = (const float*)d_in[11];
    const float* ln2_b = (const float*)d_in[12];
    const float* W1    = (const float*)d_in[13];
    const float* b1    = (const float*)d_in[14];
    const float* W2    = (const float*)d_in[15];
    const float* b2    = (const float*)d_in[16];
    float* out = (float*)d_out;

    float *h, *qkv, *vt, *ctx, *x1, *h2, *ff, *s;
    float *wqkvT, *woT, *w1T, *w2T, *bqkv;
    cudaGetSymbolAddress((void**)&h,     g_h);
    cudaGetSymbolAddress((void**)&qkv,   g_qkv);
    cudaGetSymbolAddress((void**)&vt,    g_vt);
    cudaGetSymbolAddress((void**)&ctx,   g_ctx);
    cudaGetSymbolAddress((void**)&x1,    g_x1);
    cudaGetSymbolAddress((void**)&h2,    g_h2);
    cudaGetSymbolAddress((void**)&ff,    g_ff);
    cudaGetSymbolAddress((void**)&s,     g_s);
    cudaGetSymbolAddress((void**)&wqkvT, g_wqkvT);
    cudaGetSymbolAddress((void**)&woT,   g_woT);
    cudaGetSymbolAddress((void**)&w1T,   g_w1T);
    cudaGetSymbolAddress((void**)&w2T,   g_w2T);
    cudaGetSymbolAddress((void**)&bqkv,  g_bqkv);

    const int SM_BIG = 2 * (128 + 128) * 36 * 4;  // 73728
    const int SM_PV  = 2 * (128 + 64) * 36 * 4;   // 55296

    cudaFuncSetAttribute((const void*)mma_gemm<128,128,64,32,0,false,false,true>,
                         cudaFuncAttributeMaxDynamicSharedMemorySize, SM_BIG);
    cudaFuncSetAttribute((const void*)mma_gemm<128,128,64,32,1,false,false,false>,
                         cudaFuncAttributeMaxDynamicSharedMemorySize, SM_BIG);
    cudaFuncSetAttribute((const void*)mma_gemm<128,64,32,32,2,false,false,true>,
                         cudaFuncAttributeMaxDynamicSharedMemorySize, SM_PV);
    cudaFuncSetAttribute((const void*)mma_gemm<128,128,64,32,0,false,true,false>,
                         cudaFuncAttributeMaxDynamicSharedMemorySize, SM_BIG);
    cudaFuncSetAttribute((const void*)mma_gemm<128,128,64,32,0,true,false,true>,
                         cudaFuncAttributeMaxDynamicSharedMemorySize, SM_BIG);

    // ---- weight prep (transpose + rna) ----
    bias_concat<<<9, 256>>>(bq, bk, bv, bqkv);
    transpose_rna<<<dim3(EMB/32, EMB/32), 256>>>(Wq, wqkvT,              EMB, EMB);
    transpose_rna<<<dim3(EMB/32, EMB/32), 256>>>(Wk, wqkvT + EMB*EMB,    EMB, EMB);
    transpose_rna<<<dim3(EMB/32, EMB/32), 256>>>(Wv, wqkvT + 2*EMB*EMB,  EMB, EMB);
    transpose_rna<<<dim3(EMB/32, EMB/32), 256>>>(Wo, woT,                EMB, EMB);
    transpose_rna<<<dim3(DFF/32, EMB/32), 256>>>(W1, w1T,                EMB, DFF);
    transpose_rna<<<dim3(EMB/32, DFF/32), 256>>>(W2, w2T,                DFF, EMB);

    // 1. LN1
    ln_kernel<<<NTOK, 256>>>(x, ln1_g, ln1_b, h);

    // 2. fused QKV
    mma_gemm<128,128,64,32,0,false,false,true><<<dim3(QKV3/128, NTOK/128), 256, SM_BIG>>>(
        h, wqkvT, bqkv, nullptr, qkv, NTOK, QKV3, EMB, EMB, EMB, QKV3, 1.0f);

    // 3. S = 1/8 * Q K^T
    mma_gemm<128,128,64,32,1,false,false,false><<<dim3(8, 8, BATCH*HEADS), 256, SM_BIG>>>(
        qkv, qkv + EMB, nullptr, nullptr, s, SEQ, SEQ, HD, QKV3, QKV3, SEQ, 0.125f);

    // 4. softmax
    softmax_kernel<<<dim3(SEQ, BATCH*HEADS), 256>>>(s);

    // 5. vt
    v_transpose<<<dim3(SEQ/32, HD/32, BATCH*HEADS), 256>>>(qkv, vt);

    // 6. ctx = P @ V
    mma_gemm<128,64,32,32,2,false,false,true><<<dim3(1, 8, BATCH*HEADS), 256, SM_PV>>>(
        s, vt, nullptr, nullptr, ctx, SEQ, HD, SEQ, SEQ, SEQ, EMB, 1.0f);

    // 7. x1 = ctx @ Wo + bo + x
    mma_gemm<128,128,64,32,0,false,true,false><<<dim3(EMB/128, NTOK/128), 256, SM_BIG>>>(
        ctx, woT, bo, x, x1, NTOK, EMB, EMB, EMB, EMB, EMB, 1.0f);

    // 8. LN2
    ln_kernel<<<NTOK, 256>>>(x1, ln2_g, ln2_b, h2);

    // 9. ff = rna(gelu(h2 @ W1 + b1))
    mma_gemm<128,128,64,32,0,true,false,true><<<dim3(DFF/128, NTOK/128), 256, SM_BIG>>>(
        h2, w1T, b1, nullptr, ff, NTOK, DFF, EMB, EMB, EMB, DFF, 1.0f);

    // 10. out = ff @ W2 + b2 + x1
    mma_gemm<128,128,64,32,0,false,true,false><<<dim3(EMB/128, NTOK/128), 256, SM_BIG>>>(
        ff, w2T, b2, x1, out, NTOK, EMB, DFF, DFF, DFF, EMB, 1.0f);
}

// round 4
// speedup vs baseline: 5.8135x; 1.1578x over previous
#include <cuda_runtime.h>
#include <math.h>
#include <stdint.h>

#define EMB   768
#define DFF   3072
#define NTOK  16384
#define HEADS 12
#define HD    64
#define SEQ   1024
#define BATCH 16
#define QKV3  2304

// ---------------- scratch (no allocations allowed) ----------------
__device__ float g_h   [NTOK * EMB];
__device__ float g_qkv [NTOK * QKV3];
__device__ float g_ctx [NTOK * EMB];
__device__ float g_x1  [NTOK * EMB];
__device__ float g_h2  [NTOK * EMB];
__device__ float g_ff  [NTOK * DFF];
// pre-transposed + tf32-rounded weights
__device__ float g_wqkvT[QKV3 * EMB];
__device__ float g_woT  [EMB * EMB];
__device__ float g_w1T  [DFF * EMB];
__device__ float g_w2T  [EMB * DFF];
__device__ float g_bqkv [QKV3];

// ---------------- helpers ----------------
__device__ __forceinline__ float f2tf(float f) {
    unsigned u;
    asm("cvt.rna.tf32.f32 %0, %1;" : "=r"(u) : "f"(f));
    return __uint_as_float(u);
}

__device__ __forceinline__ void mma8(float* c, const unsigned* a, const unsigned* b) {
    asm volatile(
        "mma.sync.aligned.m16n8k8.row.col.f32.tf32.tf32.f32 "
        "{%0,%1,%2,%3}, {%4,%5,%6,%7}, {%8,%9}, {%0,%1,%2,%3};"
        : "+f"(c[0]), "+f"(c[1]), "+f"(c[2]), "+f"(c[3])
        : "r"(a[0]), "r"(a[1]), "r"(a[2]), "r"(a[3]), "r"(b[0]), "r"(b[1]));
}

__device__ __forceinline__ void ldsm4(unsigned& r0, unsigned& r1, unsigned& r2,
                                      unsigned& r3, uint32_t addr) {
    asm volatile("ldmatrix.sync.aligned.m8n8.x4.shared.b16 {%0,%1,%2,%3}, [%4];"
                 : "=r"(r0), "=r"(r1), "=r"(r2), "=r"(r3) : "r"(addr));
}

#define CP_ASYNC16(dst, src) \
    asm volatile("cp.async.cg.shared.global [%0], [%1], 16;" :: "r"(dst), "l"(src))
#define CP_COMMIT() asm volatile("cp.async.commit_group;")
#define CP_WAIT1()  asm volatile("cp.async.wait_group 1;")
#define CP_WAIT0()  asm volatile("cp.async.wait_group 0;")

__device__ __forceinline__ float block_reduce_sum(float v, float* red) {
    #pragma unroll
    for (int off = 16; off > 0; off >>= 1)
        v += __shfl_xor_sync(0xffffffffu, v, off);
    int w = threadIdx.x >> 5;
    if ((threadIdx.x & 31) == 0) red[w] = v;
    __syncthreads();
    if (threadIdx.x < 32) {
        float t = (threadIdx.x < 8) ? red[threadIdx.x] : 0.0f;
        #pragma unroll
        for (int off = 4; off > 0; off >>= 1)
            t += __shfl_xor_sync(0xffffffffu, t, off);
        if (threadIdx.x == 0) red[0] = t;
    }
    __syncthreads();
    float r = red[0];
    __syncthreads();
    return r;
}

// ---------------- prep kernels ----------------
__global__ void __launch_bounds__(256) transpose_rna(
    const float* __restrict__ src, float* __restrict__ dst, int K, int N)
{
    __shared__ float t[32][33];
    const int n0 = blockIdx.x * 32;
    const int k0 = blockIdx.y * 32;
    const int tx = threadIdx.x & 31;
    const int ty = threadIdx.x >> 5;
    #pragma unroll
    for (int j = 0; j < 4; j++)
        t[ty + j * 8][tx] = src[(size_t)(k0 + ty + j * 8) * N + n0 + tx];
    __syncthreads();
    #pragma unroll
    for (int j = 0; j < 4; j++)
        dst[(size_t)(n0 + ty + j * 8) * K + k0 + tx] = f2tf(t[tx][ty + j * 8]);
}

__global__ void bias_concat(const float* bq, const float* bk, const float* bv,
                            float* out)
{
    int i = blockIdx.x * 256 + threadIdx.x;
    if (i < QKV3) {
        float v = (i < EMB) ? bq[i] : (i < 2 * EMB) ? bk[i - EMB] : bv[i - 2 * EMB];
        out[i] = v;
    }
}

// ---------------- LayerNorm (outputs tf32-rounded) ----------------
__global__ void __launch_bounds__(256) ln_kernel(
    const float* __restrict__ x, const float* __restrict__ gw,
    const float* __restrict__ bw, float* __restrict__ out)
{
    __shared__ float red[32];
    const int row = blockIdx.x;
    const float* xr = x + (size_t)row * EMB;

    float vals[3];
    float lsum = 0.0f;
    #pragma unroll
    for (int i = 0; i < 3; i++) {
        vals[i] = xr[threadIdx.x + i * 256];
        lsum += vals[i];
    }
    float mu = block_reduce_sum(lsum, red) * (1.0f / EMB);

    float ls2 = 0.0f;
    #pragma unroll
    for (int i = 0; i < 3; i++) {
        float d = vals[i] - mu;
        ls2 += d * d;
    }
    float var = block_reduce_sum(ls2, red) * (1.0f / EMB);
    float rs = rsqrtf(var + 1e-5f);

    float* outr = out + (size_t)row * EMB;
    #pragma unroll
    for (int i = 0; i < 3; i++) {
        int c = threadIdx.x + i * 256;
        outr[c] = f2tf((vals[i] - mu) * rs * gw[c] + bw[c]);
    }
}

// ---------------- fused flash attention (tf32 tensor cores) ----------------
// grid (SEQ/128, BATCH*HEADS), 256 threads (8 warps).
// Warp w handles q-rows [w*16, w*16+16) x all 128 kv cols of each tile.
#define QP 68    // K tile pitch (ldmatrix conflict-free)
#define VP 72    // V tile pitch (scalar B-frag conflict-free)
#define PP 132   // P tile pitch (scalar A-frag conflict-free)

__global__ void __launch_bounds__(256) flash_kernel(
    const float* __restrict__ qkv, float* __restrict__ ctx)
{
    extern __shared__ float fs[];
    const uint32_t base  = (uint32_t)__cvta_generic_to_shared(fs);
    const uint32_t kBase = base;                          // 2 * 128*QP floats
    const uint32_t vBase = kBase + 2u * 128 * QP * 4;     // 2 * 128*VP floats
    const uint32_t pBase = vBase + 2u * 128 * VP * 4;     // 8 * 16*PP floats
    float* Pfs = fs + 2 * 128 * QP + 2 * 128 * VP;

    const int tid  = threadIdx.x;
    const int w    = tid >> 5;
    const int lane = tid & 31;
    const int gi   = lane >> 2;
    const int li   = lane & 3;
    const int q0   = blockIdx.x * 128;
    const int z    = blockIdx.y;
    const int b    = z / HEADS, h = z % HEADS;

    const float* qptr = qkv + (size_t)(b * SEQ + q0) * QKV3 + h * HD;
    const float* kptr = qkv + (size_t)(b * SEQ) * QKV3 + EMB + h * HD;
    const float* vptr = qkv + (size_t)(b * SEQ) * QKV3 + 2 * EMB + h * HD;

    // ---- load Q tile into V-stage-1 region (reused later) ----
    {
        uint32_t dst = vBase + 128u * VP * 4;
        #pragma unroll
        for (int i = 0; i < 8; i++) {
            int idx = tid + i * 256;
            int r = idx >> 4, c = (idx & 15) * 4;
            CP_ASYNC16(dst + (uint32_t)(r * QP + c) * 4, qptr + (size_t)r * QKV3 + c);
        }
    }
    CP_COMMIT();
    CP_WAIT0();
    __syncthreads();

    // ---- extract Q fragments to registers ----
    unsigned qf[8][4];
    {
        uint32_t qb = vBase + 128u * VP * 4;
        int rowA = w * 16 + (lane & 15);
        int kqA  = (lane >> 4) * 4;
        #pragma unroll
        for (int ks = 0; ks < 8; ks++)
            ldsm4(qf[ks][0], qf[ks][1], qf[ks][2], qf[ks][3],
                  qb + (uint32_t)(rowA * QP + ks * 8 + kqA) * 4);
    }
    __syncthreads();    // V stage-1 region now free

    float m0 = -1e30f, m1 = -1e30f, l0 = 0.0f, l1 = 0.0f;
    float O[8][4];
    #pragma unroll
    for (int nt = 0; nt < 8; nt++)
        #pragma unroll
        for (int t = 0; t < 4; t++) O[nt][t] = 0.0f;

    const int rowB = ((lane >> 4) & 1) * 8 + (lane & 7);
    const int kqB  = ((lane >> 3) & 1) * 4;
    const int prow0 = w * 16 + gi;       // P row for c0/c1
    const int prow1 = prow0 + 8;         // P row for c2/c3

    // ---- prime stage 0 ----
    {
        const float* kp = kptr;
        const float* vp = vptr;
        #pragma unroll
        for (int i = 0; i < 8; i++) {
            int idx = tid + i * 256;
            int r = idx >> 4, c = (idx & 15) * 4;
            CP_ASYNC16(kBase + (uint32_t)(r * QP + c) * 4, kp + (size_t)r * QKV3 + c);
            CP_ASYNC16(vBase + (uint32_t)(r * VP + c) * 4, vp + (size_t)r * QKV3 + c);
        }
        CP_COMMIT();
    }

    for (int t = 0; t < 8; t++) {
        const int st = t & 1;
        if (t < 7) {
            const int ns = st ^ 1;
            const float* kp = kptr + (size_t)(t + 1) * 128 * QKV3;
            const float* vp = vptr + (size_t)(t + 1) * 128 * QKV3;
            uint32_t kd = kBase + (uint32_t)ns * 128 * QP * 4;
            uint32_t vd = vBase + (uint32_t)ns * 128 * VP * 4;
            #pragma unroll
            for (int i = 0; i < 8; i++) {
                int idx = tid + i * 256;
                int r = idx >> 4, c = (idx & 15) * 4;
                CP_ASYNC16(kd + (uint32_t)(r * QP + c) * 4, kp + (size_t)r * QKV3 + c);
                CP_ASYNC16(vd + (uint32_t)(r * VP + c) * 4, vp + (size_t)r * QKV3 + c);
            }
            CP_COMMIT();
            CP_WAIT1();
        } else {
            CP_WAIT0();
        }
        __syncthreads();

        // ---- S = Q K^T for this tile ----
        float acc[16][4];
        #pragma unroll
        for (int nt = 0; nt < 16; nt++)
            #pragma unroll
            for (int c = 0; c < 4; c++) acc[nt][c] = 0.0f;

        uint32_t kb = kBase + (uint32_t)st * 128 * QP * 4;
        #pragma unroll
        for (int ks = 0; ks < 8; ks++) {
            unsigned bf[16][2];
            #pragma unroll
            for (int p = 0; p < 8; p++) {
                unsigned r0, r1, r2, r3;
                ldsm4(r0, r1, r2, r3,
                      kb + (uint32_t)((rowB + p * 16) * QP + ks * 8 + kqB) * 4);
                bf[2 * p][0] = r0; bf[2 * p][1] = r1;
                bf[2 * p + 1][0] = r2; bf[2 * p + 1][1] = r3;
            }
            #pragma unroll
            for (int nt = 0; nt < 16; nt++)
                mma8(acc[nt], qf[ks], bf[nt]);
        }

        // ---- online softmax (scale 1/8 folded here) ----
        float mx0 = -1e30f, mx1 = -1e30f;
        #pragma unroll
        for (int nt = 0; nt < 16; nt++) {
            acc[nt][0] *= 0.125f; acc[nt][1] *= 0.125f;
            acc[nt][2] *= 0.125f; acc[nt][3] *= 0.125f;
            mx0 = fmaxf(mx0, fmaxf(acc[nt][0], acc[nt][1]));
            mx1 = fmaxf(mx1, fmaxf(acc[nt][2], acc[nt][3]));
        }
        mx0 = fmaxf(mx0, __shfl_xor_sync(0xffffffffu, mx0, 1));
        mx0 = fmaxf(mx0, __shfl_xor_sync(0xffffffffu, mx0, 2));
        mx1 = fmaxf(mx1, __shfl_xor_sync(0xffffffffu, mx1, 1));
        mx1 = fmaxf(mx1, __shfl_xor_sync(0xffffffffu, mx1, 2));
        float mn0 = fmaxf(m0, mx0), mn1 = fmaxf(m1, mx1);
        float a0 = __expf(m0 - mn0), a1 = __expf(m1 - mn1);
        m0 = mn0; m1 = mn1;

        float s0 = 0.0f, s1 = 0.0f;
        #pragma unroll
        for (int nt = 0; nt < 16; nt++) {
            float p0 = __expf(acc[nt][0] - mn0);
            float p1 = __expf(acc[nt][1] - mn0);
            float p2 = __expf(acc[nt][2] - mn1);
            float p3 = __expf(acc[nt][3] - mn1);
            s0 += p0 + p1; s1 += p2 + p3;
            int col = nt * 8 + 2 * li;
            *(float2*)&Pfs[prow0 * PP + col] = make_float2(f2tf(p0), f2tf(p1));
            *(float2*)&Pfs[prow1 * PP + col] = make_float2(f2tf(p2), f2tf(p3));
        }
        s0 += __shfl_xor_sync(0xffffffffu, s0, 1);
        s0 += __shfl_xor_sync(0xffffffffu, s0, 2);
        s1 += __shfl_xor_sync(0xffffffffu, s1, 1);
        s1 += __shfl_xor_sync(0xffffffffu, s1, 2);
        l0 = l0 * a0 + s0;
        l1 = l1 * a1 + s1;

        #pragma unroll
        for (int nt = 0; nt < 8; nt++) {
            O[nt][0] *= a0; O[nt][1] *= a0;
            O[nt][2] *= a1; O[nt][3] *= a1;
        }
        __syncwarp();

        // ---- O += P @ V ----
        uint32_t vb = vBase + (uint32_t)st * 128 * VP * 4;
        const unsigned* Pu = (const unsigned*)Pfs;
        #pragma unroll
        for (int kk = 0; kk < 16; kk++) {
            const int k0 = kk * 8;
            unsigned af[4];
            af[0] = Pu[prow0 * PP + k0 + li];
            af[1] = Pu[prow1 * PP + k0 + li];
            af[2] = Pu[prow0 * PP + k0 + li + 4];
            af[3] = Pu[prow1 * PP + k0 + li + 4];
            const unsigned* Vu = (const unsigned*)fs;
            uint32_t vw = (vb - base) >> 2;   // word index of V stage base
            #pragma unroll
            for (int nt = 0; nt < 8; nt++) {
                unsigned bfr[2];
                bfr[0] = Vu[vw + (k0 + li) * VP + nt * 8 + gi];
                bfr[1] = Vu[vw + (k0 + li + 4) * VP + nt * 8 + gi];
                mma8(O[nt], af, bfr);
            }
        }
        __syncthreads();
    }

    // ---- epilogue: O / l -> ctx (tf32-rounded for Wo GEMM) ----
    float inv0 = 1.0f / l0, inv1 = 1.0f / l1;
    float* out0 = ctx + (size_t)(b * SEQ + q0 + w * 16 + gi) * EMB + h * HD;
    float* out1 = out0 + (size_t)8 * EMB;
    #pragma unroll
    for (int nt = 0; nt < 8; nt++) {
        int col = nt * 8 + 2 * li;
        *(float2*)(out0 + col) = make_float2(f2tf(O[nt][0] * inv0), f2tf(O[nt][1] * inv0));
        *(float2*)(out1 + col) = make_float2(f2tf(O[nt][2] * inv1), f2tf(O[nt][3] * inv1));
    }
}

// ---------------- tf32 tensor-core GEMM, cp.async double-buffered, ldmatrix ----
template<int BM, int BN, int WM, int WN, bool DO_GELU, bool DO_RESID, bool RNA_OUT>
__global__ void __launch_bounds__(256) mma_gemm(
    const float* __restrict__ A, const float* __restrict__ B,
    const float* __restrict__ bias, const float* __restrict__ R,
    float* __restrict__ C, int M, int N, int K,
    int lda, int ldb, int ldc, float scale)
{
    constexpr int BK = 32, BKP = 36;
    constexpr int MT = WM / 16;
    constexpr int NT = WN / 8;
    constexpr int WARPS_N = BN / WN;
    constexpr int STAGE = (BM + BN) * BKP;

    extern __shared__ unsigned smem[];
    const uint32_t base = (uint32_t)__cvta_generic_to_shared(smem);

    const int tid  = threadIdx.x;
    const int w    = tid >> 5;
    const int lane = tid & 31;
    const int gi   = lane >> 2;
    const int li   = lane & 3;
    const int wn   = w % WARPS_N;
    const int wm   = w / WARPS_N;
    const int bm   = blockIdx.y * BM;
    const int bn   = blockIdx.x * BN;

    const int rowA = wm * WM + (lane & 15);
    const int kqA  = (lane >> 4) * 4;
    const int rowB = wn * WN + ((lane >> 4) & 1) * 8 + (lane & 7);
    const int kqB  = ((lane >> 3) & 1) * 4;

    auto load_tile = [&](int k0, int st) {
        uint32_t sA = base + (uint32_t)st * STAGE * 4;
        uint32_t sB = sA + BM * BKP * 4;
        #pragma unroll
        for (int i = 0; i < BM / 32; i++) {
            int idx = tid + i * 256;
            int r = idx >> 3, c = (idx & 7) * 4;
            CP_ASYNC16(sA + (uint32_t)(r * BKP + c) * 4,
                       A + (size_t)(bm + r) * lda + k0 + c);
        }
        #pragma unroll
        for (int i = 0; i < BN / 32; i++) {
            int idx = tid + i * 256;
            int r = idx >> 3, c = (idx & 7) * 4;
            CP_ASYNC16(sB + (uint32_t)(r * BKP + c) * 4,
                       B + (size_t)(bn + r) * ldb + k0 + c);
        }
    };

    float acc[MT][NT][4];
    #pragma unroll
    for (int i = 0; i < MT; i++)
        #pragma unroll
        for (int j = 0; j < NT; j++)
            #pragma unroll
            for (int t = 0; t < 4; t++) acc[i][j][t] = 0.0f;

    const int iters = K / BK;
    load_tile(0, 0);
    CP_COMMIT();

    for (int it = 0; it < iters; ++it) {
        const int st = it & 1;
        if (it + 1 < iters) load_tile((it + 1) * BK, st ^ 1);
        CP_COMMIT();
        CP_WAIT1();
        __syncthreads();

        uint32_t sA = base + (uint32_t)st * STAGE * 4;
        uint32_t sB = sA + BM * BKP * 4;

        #pragma unroll
        for (int ks = 0; ks < BK / 8; ks++) {
            const int kb = ks * 8;
            unsigned af[MT][4];
            #pragma unroll
            for (int mt = 0; mt < MT; mt++) {
                uint32_t ad = sA + (uint32_t)((rowA + mt * 16) * BKP + kb + kqA) * 4;
                ldsm4(af[mt][0], af[mt][1], af[mt][2], af[mt][3], ad);
            }
            unsigned bf[NT][2];
            #pragma unroll
            for (int p = 0; p < NT / 2; p++) {
                uint32_t ad = sB + (uint32_t)((rowB + p * 16) * BKP + kb + kqB) * 4;
                unsigned r0, r1, r2, r3;
                ldsm4(r0, r1, r2, r3, ad);
                bf[2 * p][0] = r0; bf[2 * p][1] = r1;
                bf[2 * p + 1][0] = r2; bf[2 * p + 1][1] = r3;
            }
            #pragma unroll
            for (int mt = 0; mt < MT; mt++)
                #pragma unroll
                for (int nt = 0; nt < NT; nt++)
                    mma8(acc[mt][nt], af[mt], bf[nt]);
        }
        __syncthreads();
    }

    #pragma unroll
    for (int mt = 0; mt < MT; mt++) {
        #pragma unroll
        for (int nt = 0; nt < NT; nt++) {
            int row = bm + wm * WM + mt * 16 + gi;
            int col = bn + wn * WN + nt * 8 + 2 * li;
            float bi0 = 0.0f, bi1 = 0.0f;
            if (bias) { bi0 = bias[col]; bi1 = bias[col + 1]; }
            #pragma unroll
            for (int half = 0; half < 2; half++) {
                int rr = row + half * 8;
                float v0 = acc[mt][nt][half * 2 + 0] * scale + bi0;
                float v1 = acc[mt][nt][half * 2 + 1] * scale + bi1;
                if (DO_GELU) {
                    v0 = 0.5f * v0 * (1.0f + erff(v0 * 0.70710678118654752f));
                    v1 = 0.5f * v1 * (1.0f + erff(v1 * 0.70710678118654752f));
                }
                if (DO_RESID) {
                    float2 r2 = *(const float2*)(R + (size_t)rr * ldc + col);
                    v0 += r2.x; v1 += r2.y;
                }
                if (RNA_OUT) { v0 = f2tf(v0); v1 = f2tf(v1); }
                *(float2*)(C + (size_t)rr * ldc + col) = make_float2(v0, v1);
            }
        }
    }
}

// ---------------- launch ----------------
extern "C" void kernel_launch(void* const* d_in, const int* in_sizes, int n_in,
                              void* d_out, int out_size)
{
    const float* x     = (const float*)d_in[0];
    const float* ln1_g = (const float*)d_in[1];
    const float* ln1_b = (const float*)d_in[2];
    const float* Wq    = (const float*)d_in[3];
    const float* bq    = (const float*)d_in[4];
    const float* Wk    = (const float*)d_in[5];
    const float* bk    = (const float*)d_in[6];
    const float* Wv    = (const float*)d_in[7];
    const float* bv    = (const float*)d_in[8];
    const float* Wo    = (const float*)d_in[9];
    const float* bo    = (const float*)d_in[10];
    const float* ln2_g = (const float*)d_in[11];
    const float* ln2_b = (const float*)d_in[12];
    const float* W1    = (const float*)d_in[13];
    const float* b1    = (const float*)d_in[14];
    const float* W2    = (const float*)d_in[15];
    const float* b2    = (const float*)d_in[16];
    float* out = (float*)d_out;

    float *h, *qkv, *ctx, *x1, *h2, *ff;
    float *wqkvT, *woT, *w1T, *w2T, *bqkv;
    cudaGetSymbolAddress((void**)&h,     g_h);
    cudaGetSymbolAddress((void**)&qkv,   g_qkv);
    cudaGetSymbolAddress((void**)&ctx,   g_ctx);
    cudaGetSymbolAddress((void**)&x1,    g_x1);
    cudaGetSymbolAddress((void**)&h2,    g_h2);
    cudaGetSymbolAddress((void**)&ff,    g_ff);
    cudaGetSymbolAddress((void**)&wqkvT, g_wqkvT);
    cudaGetSymbolAddress((void**)&woT,   g_woT);
    cudaGetSymbolAddress((void**)&w1T,   g_w1T);
    cudaGetSymbolAddress((void**)&w2T,   g_w2T);
    cudaGetSymbolAddress((void**)&bqkv,  g_bqkv);

    const int SM_BIG   = 2 * (128 + 128) * 36 * 4;                       // 73728
    const int SM_FLASH = (2 * 128 * QP + 2 * 128 * VP + 8 * 16 * PP) * 4; // 210944

    cudaFuncSetAttribute((const void*)mma_gemm<128,128,64,32,false,false,true>,
                         cudaFuncAttributeMaxDynamicSharedMemorySize, SM_BIG);
    cudaFuncSetAttribute((const void*)mma_gemm<128,128,64,32,false,true,false>,
                         cudaFuncAttributeMaxDynamicSharedMemorySize, SM_BIG);
    cudaFuncSetAttribute((const void*)mma_gemm<128,128,64,32,true,false,true>,
                         cudaFuncAttributeMaxDynamicSharedMemorySize, SM_BIG);
    cudaFuncSetAttribute((const void*)flash_kernel,
                         cudaFuncAttributeMaxDynamicSharedMemorySize, SM_FLASH);

    // ---- weight prep (transpose + rna) ----
    bias_concat<<<9, 256>>>(bq, bk, bv, bqkv);
    transpose_rna<<<dim3(EMB/32, EMB/32), 256>>>(Wq, wqkvT,              EMB, EMB);
    transpose_rna<<<dim3(EMB/32, EMB/32), 256>>>(Wk, wqkvT + EMB*EMB,    EMB, EMB);
    transpose_rna<<<dim3(EMB/32, EMB/32), 256>>>(Wv, wqkvT + 2*EMB*EMB,  EMB, EMB);
    transpose_rna<<<dim3(EMB/32, EMB/32), 256>>>(Wo, woT,                EMB, EMB);
    transpose_rna<<<dim3(DFF/32, EMB/32), 256>>>(W1, w1T,                EMB, DFF);
    transpose_rna<<<dim3(EMB/32, DFF/32), 256>>>(W2, w2T,                DFF, EMB);

    // 1. LN1
    ln_kernel<<<NTOK, 256>>>(x, ln1_g, ln1_b, h);

    // 2. fused QKV (outputs tf32-rounded)
    mma_gemm<128,128,64,32,false,false,true><<<dim3(QKV3/128, NTOK/128), 256, SM_BIG>>>(
        h, wqkvT, bqkv, nullptr, qkv, NTOK, QKV3, EMB, EMB, EMB, QKV3, 1.0f);

    // 3. fused flash attention -> ctx (tf32-rounded)
    flash_kernel<<<dim3(SEQ/128, BATCH*HEADS), 256, SM_FLASH>>>(qkv, ctx);

    // 4. x1 = ctx @ Wo + bo + x
    mma_gemm<128,128,64,32,false,true,false><<<dim3(EMB/128, NTOK/128), 256, SM_BIG>>>(
        ctx, woT, bo, x, x1, NTOK, EMB, EMB, EMB, EMB, EMB, 1.0f);

    // 5. LN2
    ln_kernel<<<NTOK, 256>>>(x1, ln2_g, ln2_b, h2);

    // 6. ff = rna(gelu(h2 @ W1 + b1))
    mma_gemm<128,128,64,32,true,false,true><<<dim3(DFF/128, NTOK/128), 256, SM_BIG>>>(
        h2, w1T, b1, nullptr, ff, NTOK, DFF, EMB, EMB, EMB, DFF, 1.0f);

    // 7. out = ff @ W2 + b2 + x1
    mma_gemm<128,128,64,32,false,true,false><<<dim3(EMB/128, NTOK/128), 256, SM_BIG>>>(
        ff, w2T, b2, x1, out, NTOK, EMB, DFF, DFF, DFF, EMB, 1.0f);
}